// round 6
// baseline (speedup 1.0000x reference)
#include <cuda_runtime.h>
#include <cuda_fp16.h>
#include <cstdint>

// Shapes (fixed per reference): B=16, C=512, H=W=64, S=512
#define B_   16
#define C_   512
#define HW_  4096
#define S_   512
#define NCC  16         // C-chunks in pass kA
#define CCW  (C_/NCC)   // 32 channels per chunk

// Scratch (no allocation allowed — device globals)
__device__ __align__(16) __half g_xp[(size_t)B_ * C_ * HW_]; // 67 MB fp16 x'
__device__ __align__(16) float g_part[NCC * B_ * HW_];       // 4 MB partial sumsq
__device__ __align__(16) float g_invrms[B_ * HW_];           // 262 KB
__device__ __align__(16) float g_style[B_ * 2 * C_];         // 64 KB

#define KA_BLOCKS   1024
#define GEMM_BLOCKS 256

// ---------------------------------------------------------------------------
// kA (fused): blocks [0,1024): x' = leaky(x + nw[c]*noise) for a 32-channel
//   chunk x 1024-pixel tile; store x' as fp16 to g_xp (L2-resident) and a
//   per-pixel partial sum of squares to g_part.
//   blocks [1024,1280): style GEMM s[b,:] = style[b,:] @ W + bias (hidden).
// ---------------------------------------------------------------------------
__global__ __launch_bounds__(256) void kA(
    const float* __restrict__ x,
    const float* __restrict__ noise,
    const float* __restrict__ nw,
    const float* __restrict__ style,
    const float* __restrict__ W,
    const float* __restrict__ bias)
{
    const int tid = threadIdx.x;

    if (blockIdx.x < KA_BLOCKS) {
        __shared__ float snw[CCW];
        const int cc   = blockIdx.x & 15;
        const int tile = (blockIdx.x >> 4) & 3;
        const int b    = blockIdx.x >> 6;
        if (tid < CCW) snw[tid] = nw[cc * CCW + tid];
        __syncthreads();

        const int px = tile * 1024 + tid * 4;
        const float4 nz = *(const float4*)(noise + b * HW_ + px);
        const size_t base = ((size_t)b * C_ + cc * CCW) * HW_ + px;
        const float* xp = x + base;

        float4 acc = make_float4(0.f, 0.f, 0.f, 0.f);
#pragma unroll
        for (int c = 0; c < CCW; c++) {
            const float4 xv = __ldcs((const float4*)(xp + (size_t)c * HW_));
            float v0 = fmaf(snw[c], nz.x, xv.x);
            float v1 = fmaf(snw[c], nz.y, xv.y);
            float v2 = fmaf(snw[c], nz.z, xv.z);
            float v3 = fmaf(snw[c], nz.w, xv.w);
            v0 = (v0 >= 0.f) ? v0 : 0.2f * v0;
            v1 = (v1 >= 0.f) ? v1 : 0.2f * v1;
            v2 = (v2 >= 0.f) ? v2 : 0.2f * v2;
            v3 = (v3 >= 0.f) ? v3 : 0.2f * v3;
            acc.x = fmaf(v0, v0, acc.x);
            acc.y = fmaf(v1, v1, acc.y);
            acc.z = fmaf(v2, v2, acc.z);
            acc.w = fmaf(v3, v3, acc.w);
            union { __half2 h[2]; uint2 u; } cv;
            cv.h[0] = __floats2half2_rn(v0, v1);
            cv.h[1] = __floats2half2_rn(v2, v3);
            *(uint2*)(g_xp + base + (size_t)c * HW_) = cv.u;
        }
        *(float4*)(g_part + ((size_t)cc * B_ + b) * HW_ + px) = acc;
    } else {
        // ----- style GEMM -----
        __shared__ float ss[S_];
        __shared__ float sp[256];
        const int gb = blockIdx.x - KA_BLOCKS;   // 0..255
        const int b = gb >> 4, chunk = gb & 15;  // 16 chunks of 64 cols
        for (int i = tid; i < S_; i += 256) ss[i] = style[b * S_ + i];
        __syncthreads();

        const int col = chunk * 64 + (tid & 63);
        const int k0  = (tid >> 6) * 128;        // 4 K-slices of 128
        float acc = 0.f;
#pragma unroll 8
        for (int k = k0; k < k0 + 128; k++)
            acc = fmaf(ss[k], __ldg(W + (size_t)k * 1024 + col), acc);
        sp[tid] = acc;
        __syncthreads();
        if (tid < 64)
            g_style[b * 1024 + col] = sp[tid] + sp[tid + 64] + sp[tid + 128]
                                    + sp[tid + 192] + __ldg(bias + col);
    }
}

// ---------------------------------------------------------------------------
// kComb: combine 16 partials -> invrms. 64 blocks, 256 thr x 4 px (float4).
// ---------------------------------------------------------------------------
__global__ __launch_bounds__(256) void kComb()
{
    const int b = blockIdx.x >> 2, tile = blockIdx.x & 3;
    const int px = tile * 1024 + threadIdx.x * 4;
    float4 s = make_float4(0.f, 0.f, 0.f, 0.f);
#pragma unroll
    for (int cc = 0; cc < NCC; cc++) {
        const float4 p = *(const float4*)(g_part + ((size_t)cc * B_ + b) * HW_ + px);
        s.x += p.x; s.y += p.y; s.z += p.z; s.w += p.w;
    }
    float4 r;
    r.x = rsqrtf(s.x * (1.f / (float)C_) + 1e-8f);
    r.y = rsqrtf(s.y * (1.f / (float)C_) + 1e-8f);
    r.z = rsqrtf(s.z * (1.f / (float)C_) + 1e-8f);
    r.w = rsqrtf(s.w * (1.f / (float)C_) + 1e-8f);
    *(float4*)(g_invrms + b * HW_ + px) = r;
}

// ---------------------------------------------------------------------------
// kB: one (b,c) plane per block (8192 blocks, 256 thr).
//   Read x' (fp16, L2-hit), y = x' * invrms, block-reduce mean/var,
//   out = y*(istd*scale) + (shift - mean*istd*scale).
//   After consuming the plane, discard its L2 lines (no DRAM writeback).
// ---------------------------------------------------------------------------
__global__ __launch_bounds__(256) void kB(
    float* __restrict__ out)
{
    const int b = blockIdx.x >> 9;
    const int c = blockIdx.x & (C_ - 1);
    const size_t plane = ((size_t)b * C_ + c) * HW_;

    const uint4* xp = (const uint4*)(g_xp + plane);       // 512 x 16B (8 px)
    const float4* ip = (const float4*)(g_invrms + (size_t)b * HW_);
    const int tid = threadIdx.x;

    float4 y[4];                                          // 16 px / thread
    float sum = 0.f, sumsq = 0.f;

#pragma unroll
    for (int j = 0; j < 2; j++) {
        const int idx = tid + j * 256;                    // 0..511
        const uint4 raw = xp[idx];
        const float4 iv0 = __ldg(ip + idx * 2);
        const float4 iv1 = __ldg(ip + idx * 2 + 1);
        float2 p0 = __half22float2(*(const __half2*)&raw.x);
        float2 p1 = __half22float2(*(const __half2*)&raw.y);
        float2 p2 = __half22float2(*(const __half2*)&raw.z);
        float2 p3 = __half22float2(*(const __half2*)&raw.w);
        float4 a, d4;
        a.x = p0.x * iv0.x; a.y = p0.y * iv0.y;
        a.z = p1.x * iv0.z; a.w = p1.y * iv0.w;
        d4.x = p2.x * iv1.x; d4.y = p2.y * iv1.y;
        d4.z = p3.x * iv1.z; d4.w = p3.y * iv1.w;
        y[j * 2]     = a;
        y[j * 2 + 1] = d4;
        sum   += a.x + a.y + a.z + a.w + d4.x + d4.y + d4.z + d4.w;
        sumsq += a.x*a.x + a.y*a.y + a.z*a.z + a.w*a.w
               + d4.x*d4.x + d4.y*d4.y + d4.z*d4.z + d4.w*d4.w;
    }

    // All loads consumed into registers -> safe to discard the plane's lines.
    __syncthreads();
    if (tid < 64) {   // 8 KB plane = 64 x 128B lines
        const char* lp = (const char*)(g_xp + plane) + tid * 128;
        asm volatile("discard.global.L2 [%0], 128;" :: "l"(lp) : "memory");
    }

    // Block reduction
    const int lane = tid & 31, warp = tid >> 5;
#pragma unroll
    for (int off = 16; off > 0; off >>= 1) {
        sum   += __shfl_xor_sync(0xFFFFFFFFu, sum,   off);
        sumsq += __shfl_xor_sync(0xFFFFFFFFu, sumsq, off);
    }
    __shared__ float s_sum[8], s_sq[8], s_stats[2];
    if (lane == 0) { s_sum[warp] = sum; s_sq[warp] = sumsq; }
    __syncthreads();
    if (tid == 0) {
        float ts = 0.f, tq = 0.f;
#pragma unroll
        for (int k = 0; k < 8; k++) { ts += s_sum[k]; tq += s_sq[k]; }
        const float mean = ts * (1.f / (float)HW_);
        const float var  = tq * (1.f / (float)HW_) - mean * mean;
        s_stats[0] = mean;
        s_stats[1] = rsqrtf(var + 1e-5f);
    }
    __syncthreads();
    const float mean = s_stats[0];
    const float istd = s_stats[1];

    const float scale = g_style[b * 1024 + c] + 1.f;   // s[:,0] + 1
    const float shift = g_style[b * 1024 + C_ + c];    // s[:,1]
    const float aa = istd * scale;
    const float dd = shift - mean * aa;

    float4* op = (float4*)(out + plane);
#pragma unroll
    for (int j = 0; j < 2; j++) {
        const int idx = tid + j * 256;
#pragma unroll
        for (int h = 0; h < 2; h++) {
            const float4 yv = y[j * 2 + h];
            float4 ov;
            ov.x = fmaf(yv.x, aa, dd);
            ov.y = fmaf(yv.y, aa, dd);
            ov.z = fmaf(yv.z, aa, dd);
            ov.w = fmaf(yv.w, aa, dd);
            __stcs(op + idx * 2 + h, ov);
        }
    }
}

// ---------------------------------------------------------------------------
// Inputs (metadata order): x, noise, style, noise_weight, lin_W, lin_b
// Output: float32 [B, C, H, W]
// ---------------------------------------------------------------------------
extern "C" void kernel_launch(void* const* d_in, const int* in_sizes, int n_in,
                              void* d_out, int out_size)
{
    const float* x     = (const float*)d_in[0];
    const float* noise = (const float*)d_in[1];
    const float* style = (const float*)d_in[2];
    const float* nw    = (const float*)d_in[3];
    const float* lin_W = (const float*)d_in[4];
    const float* lin_b = (const float*)d_in[5];
    float* out = (float*)d_out;

    kA<<<KA_BLOCKS + GEMM_BLOCKS, 256>>>(x, noise, nw, style, lin_W, lin_b);
    kComb<<<64, 256>>>();
    kB<<<B_ * C_, 256>>>(out);
}

// round 9
// speedup vs baseline: 1.1092x; 1.1092x over previous
#include <cuda_runtime.h>
#include <cstdint>

// Shapes (fixed per reference): B=16, C=512, H=W=64, S=512
#define B_   16
#define C_   512
#define HW_  4096
#define S_   512
#define NCC  8          // C-chunks in pass kA
#define CCW  (C_/NCC)   // 64 channels per chunk

// Scratch (no allocation allowed — device globals)
__device__ __align__(16) float g_part[NCC * B_ * HW_];  // 2 MB partial sumsq
__device__ __align__(16) float g_invrms[B_ * HW_];      // 262 KB
__device__ __align__(16) float g_style[B_ * 2 * C_];    // 64 KB

#define GEMM_BLOCKS 256
#define K1_BLOCKS   512   // 8 cc x 4 tiles x 16 b

// ---------------------------------------------------------------------------
// kA (fused):
//   blocks [0,256):   style GEMM s[b,:] = style[b,:] @ W + bias (first wave,
//                     latency hidden under the streaming below)
//   blocks [256,768): partial sum-of-squares of x' = leaky(x + nw[c]*noise)
//                     over a 64-channel chunk, 1024-pixel tile.
//                     256 thr x 4 px (float4), 64-deep channel loop.
// ---------------------------------------------------------------------------
__global__ __launch_bounds__(256) void kA(
    const float* __restrict__ x,
    const float* __restrict__ noise,
    const float* __restrict__ nw,
    const float* __restrict__ style,
    const float* __restrict__ W,
    const float* __restrict__ bias)
{
    const int tid = threadIdx.x;

    if (blockIdx.x < GEMM_BLOCKS) {
        // ----- style GEMM -----
        __shared__ float ss[S_];
        __shared__ float sp[256];
        const int gb = blockIdx.x;               // 0..255
        const int b = gb >> 4, chunk = gb & 15;  // 16 chunks of 64 cols
        for (int i = tid; i < S_; i += 256) ss[i] = style[b * S_ + i];
        __syncthreads();

        const int col = chunk * 64 + (tid & 63);
        const int k0  = (tid >> 6) * 128;        // 4 K-slices of 128
        float acc = 0.f;
#pragma unroll 8
        for (int k = k0; k < k0 + 128; k++)
            acc = fmaf(ss[k], __ldg(W + (size_t)k * 1024 + col), acc);
        sp[tid] = acc;
        __syncthreads();
        if (tid < 64)
            g_style[b * 1024 + col] = sp[tid] + sp[tid + 64] + sp[tid + 128]
                                    + sp[tid + 192] + __ldg(bias + col);
    } else {
        __shared__ float snw[CCW];
        const int bx   = blockIdx.x - GEMM_BLOCKS;  // 0..511
        const int cc   = bx & 7;
        const int tile = (bx >> 3) & 3;
        const int b    = bx >> 5;
        if (tid < CCW) snw[tid] = nw[cc * CCW + tid];
        __syncthreads();

        const int px = tile * 1024 + tid * 4;
        const float4 nz = *(const float4*)(noise + b * HW_ + px);
        const float* xp = x + ((size_t)b * C_ + cc * CCW) * HW_ + px;

        float4 acc = make_float4(0.f, 0.f, 0.f, 0.f);
#pragma unroll 8
        for (int c = 0; c < CCW; c++) {
            const float4 xv = __ldcs((const float4*)(xp + (size_t)c * HW_));
            const float w = snw[c];
            float v;
            v = fmaf(w, nz.x, xv.x); v = (v >= 0.f) ? v : 0.2f * v; acc.x = fmaf(v, v, acc.x);
            v = fmaf(w, nz.y, xv.y); v = (v >= 0.f) ? v : 0.2f * v; acc.y = fmaf(v, v, acc.y);
            v = fmaf(w, nz.z, xv.z); v = (v >= 0.f) ? v : 0.2f * v; acc.z = fmaf(v, v, acc.z);
            v = fmaf(w, nz.w, xv.w); v = (v >= 0.f) ? v : 0.2f * v; acc.w = fmaf(v, v, acc.w);
        }
        *(float4*)(g_part + ((size_t)cc * B_ + b) * HW_ + px) = acc;
    }
}

// ---------------------------------------------------------------------------
// kComb: combine 8 partials -> invrms. 128 blocks, 256 thr x 2 px (float2).
// ---------------------------------------------------------------------------
__global__ __launch_bounds__(256) void kComb()
{
    const int b = blockIdx.x >> 3, tile = blockIdx.x & 7;
    const int px = tile * 512 + threadIdx.x * 2;
    float2 s = make_float2(0.f, 0.f);
#pragma unroll
    for (int cc = 0; cc < NCC; cc++) {
        const float2 p = *(const float2*)(g_part + ((size_t)cc * B_ + b) * HW_ + px);
        s.x += p.x; s.y += p.y;
    }
    float2 r;
    r.x = rsqrtf(s.x * (1.f / (float)C_) + 1e-8f);
    r.y = rsqrtf(s.y * (1.f / (float)C_) + 1e-8f);
    *(float2*)(g_invrms + b * HW_ + px) = r;
}

// ---------------------------------------------------------------------------
// kB: one (b,c) plane per block (8192 blocks, 256 thr x 16 px).
//   y = leaky(x + nw[c]*noise) * invrms (regs), block-reduce mean/var,
//   out = y*(istd*scale) + (shift - mean*istd*scale)
// x via __ldcs (evict-first), out via __stcs; noise/invrms stay L2-hot.
// ---------------------------------------------------------------------------
__global__ __launch_bounds__(256) void kB(
    const float* __restrict__ x,
    const float* __restrict__ noise,
    const float* __restrict__ nw,
    float* __restrict__ out)
{
    const int b = blockIdx.x >> 9;
    const int c = blockIdx.x & (C_ - 1);
    const size_t plane = ((size_t)b * C_ + c) * HW_;

    const float4* xp = (const float4*)(x + plane);
    const float4* np = (const float4*)(noise + (size_t)b * HW_);
    const float4* ip = (const float4*)(g_invrms + b * HW_);
    const float w = __ldg(nw + c);
    const int tid = threadIdx.x;

    float4 y[4];
    float sum = 0.f, sumsq = 0.f;

#pragma unroll
    for (int j = 0; j < 4; j++) {
        const int i = tid + j * 256;
        const float4 xv = __ldcs(xp + i);
        const float4 nv = __ldg(np + i);
        const float4 iv = __ldg(ip + i);
        float4 yv;
        float v;
        v = fmaf(w, nv.x, xv.x); v = (v >= 0.f) ? v : 0.2f * v; yv.x = v * iv.x;
        v = fmaf(w, nv.y, xv.y); v = (v >= 0.f) ? v : 0.2f * v; yv.y = v * iv.y;
        v = fmaf(w, nv.z, xv.z); v = (v >= 0.f) ? v : 0.2f * v; yv.z = v * iv.z;
        v = fmaf(w, nv.w, xv.w); v = (v >= 0.f) ? v : 0.2f * v; yv.w = v * iv.w;
        y[j] = yv;
        sum   += yv.x + yv.y + yv.z + yv.w;
        sumsq += yv.x * yv.x + yv.y * yv.y + yv.z * yv.z + yv.w * yv.w;
    }

    const int lane = tid & 31, warp = tid >> 5;
#pragma unroll
    for (int off = 16; off > 0; off >>= 1) {
        sum   += __shfl_xor_sync(0xFFFFFFFFu, sum,   off);
        sumsq += __shfl_xor_sync(0xFFFFFFFFu, sumsq, off);
    }
    __shared__ float s_sum[8], s_sq[8], s_stats[2];
    if (lane == 0) { s_sum[warp] = sum; s_sq[warp] = sumsq; }
    __syncthreads();
    if (tid == 0) {
        float ts = 0.f, tq = 0.f;
#pragma unroll
        for (int k = 0; k < 8; k++) { ts += s_sum[k]; tq += s_sq[k]; }
        const float mean = ts * (1.f / (float)HW_);
        const float var  = tq * (1.f / (float)HW_) - mean * mean;
        s_stats[0] = mean;
        s_stats[1] = rsqrtf(var + 1e-5f);
    }
    __syncthreads();
    const float mean = s_stats[0];
    const float istd = s_stats[1];

    const float scale = g_style[b * 1024 + c] + 1.f;   // s[:,0] + 1
    const float shift = g_style[b * 1024 + C_ + c];    // s[:,1]
    const float a = istd * scale;
    const float d = shift - mean * a;

    float4* op = (float4*)(out + plane);
#pragma unroll
    for (int j = 0; j < 4; j++) {
        const int i = tid + j * 256;
        const float4 yv = y[j];
        float4 ov;
        ov.x = fmaf(yv.x, a, d);
        ov.y = fmaf(yv.y, a, d);
        ov.z = fmaf(yv.z, a, d);
        ov.w = fmaf(yv.w, a, d);
        __stcs(op + i, ov);
    }
}

// ---------------------------------------------------------------------------
// Inputs (metadata order): x, noise, style, noise_weight, lin_W, lin_b
// Output: float32 [B, C, H, W]
// ---------------------------------------------------------------------------
extern "C" void kernel_launch(void* const* d_in, const int* in_sizes, int n_in,
                              void* d_out, int out_size)
{
    const float* x     = (const float*)d_in[0];
    const float* noise = (const float*)d_in[1];
    const float* style = (const float*)d_in[2];
    const float* nw    = (const float*)d_in[3];
    const float* lin_W = (const float*)d_in[4];
    const float* lin_b = (const float*)d_in[5];
    float* out = (float*)d_out;

    kA<<<GEMM_BLOCKS + K1_BLOCKS, 256>>>(x, noise, nw, style, lin_W, lin_b);
    kComb<<<128, 256>>>();
    kB<<<B_ * C_, 256>>>(x, noise, nw, out);
}